// round 10
// baseline (speedup 1.0000x reference)
#include <cuda_runtime.h>
#include <cuda_bf16.h>
#include <cuda_fp16.h>
#include <cstdint>

// Sizes
#define W_WORDS 4096
#define LCH 32
#define D2 512
#define D4 1024
#define KDIM 1536   // 3*512

// GEMM tiling
#define GM 128
#define GN 64
#define GK 64
#define NK (KDIM / GK)            // 24
#define A_TILE (GM * GK * 2)      // 16384 B (fp16)
#define B_TILE (GN * GK * 2)      // 8192 B
#define STAGE_B (A_TILE + B_TILE) // 24576
#define NSTAGE 3
#define SMEM_DYN_GEMM (NSTAGE * STAGE_B)    // 73728

// ---------------- scratch ----------------
__device__ __align__(128) __half g_Wth[3 * 256 * 256];       // char conv w transposed, fp16
__device__ __align__(128) __half g_Th[3 * 128 * 256];        // fp16 lookup tables
__device__ __align__(128) __half g_ua[(W_WORDS + 2) * D2];   // u in fp16
__device__ __align__(128) __half g_Bh[D2 * KDIM];            // B fp16 [o][p] K-major
__device__ __align__(128) unsigned g_rkeys[D2];

// ---------------- helpers ----------------
__device__ __forceinline__ uint32_t smem_u32(const void* p) {
    uint32_t a;
    asm("{ .reg .u64 t; cvta.to.shared.u64 t, %1; cvt.u32.u64 %0, t; }" : "=r"(a) : "l"(p));
    return a;
}
__device__ __forceinline__ void ldmx4(uint32_t* r, uint32_t addr) {
    asm volatile("ldmatrix.sync.aligned.m8n8.x4.shared.b16 {%0,%1,%2,%3}, [%4];"
                 : "=r"(r[0]), "=r"(r[1]), "=r"(r[2]), "=r"(r[3]) : "r"(addr));
}
__device__ __forceinline__ void mma_f16(float* c, const uint32_t* a, uint32_t b0, uint32_t b1) {
    asm volatile("mma.sync.aligned.m16n8k16.row.col.f32.f16.f16.f32 "
                 "{%0,%1,%2,%3}, {%4,%5,%6,%7}, {%8,%9}, {%0,%1,%2,%3};"
                 : "+f"(c[0]), "+f"(c[1]), "+f"(c[2]), "+f"(c[3])
                 : "r"(a[0]), "r"(a[1]), "r"(a[2]), "r"(a[3]), "r"(b0), "r"(b1));
}
__device__ __forceinline__ void cp16(uint32_t dst, const void* src) {
    asm volatile("cp.async.cg.shared.global [%0], [%1], 16;" :: "r"(dst), "l"(src));
}
#define CP_COMMIT() asm volatile("cp.async.commit_group;" ::: "memory")
#define CP_WAIT1()  asm volatile("cp.async.wait_group 1;" ::: "memory")

// ---------------- prep: transpose char-w (fp16) + convert sentence-w (merged) ----------------
__global__ void k_prep(const float* __restrict__ wc, const float* __restrict__ ws) {
    int b = blockIdx.x;
    if (b < 768) {                 // wc: [d][i][k] -> g_Wth[k][i][d]
        int k = b / 256, i = b % 256;
        int d = threadIdx.x;
        g_Wth[k * 65536 + i * 256 + d] = __float2half(wc[d * 768 + i * 3 + k]);
    } else {                       // ws -> Bh, K-major [o][p]
        int o = b - 768;           // 512
        for (int p = threadIdx.x; p < KDIM; p += 256) {
            int kk = p >> 9, i = p & 511;
            g_Bh[o * KDIM + p] = __float2half(ws[o * KDIM + i * 3 + kk]);
        }
        if (o == 0) { g_rkeys[threadIdx.x] = 0u; g_rkeys[threadIdx.x + 256] = 0u; }
    }
}

// ---------------- char tables: fp16 weights, fp32 accum, fp16 store ----------------
__global__ void k_tables(const float* __restrict__ chr_emb) {
    __shared__ float ce[2][256];
    int d = threadIdx.x;
    int c0 = blockIdx.x * 2;
    ce[0][d] = chr_emb[c0 * 256 + d];
    ce[1][d] = chr_emb[(c0 + 1) * 256 + d];
    __syncthreads();
    float a00 = 0.f, a01 = 0.f, a02 = 0.f, a10 = 0.f, a11 = 0.f, a12 = 0.f;
    #pragma unroll 8
    for (int i = 0; i < 256; i++) {
        float e0 = ce[0][i], e1 = ce[1][i];
        float w0 = __half2float(g_Wth[i * 256 + d]);
        float w1 = __half2float(g_Wth[65536 + i * 256 + d]);
        float w2 = __half2float(g_Wth[131072 + i * 256 + d]);
        a00 += e0 * w0; a01 += e0 * w1; a02 += e0 * w2;
        a10 += e1 * w0; a11 += e1 * w1; a12 += e1 * w2;
    }
    g_Th[c0 * 256 + d]                  = __float2half(a00);
    g_Th[32768 + c0 * 256 + d]          = __float2half(a01);
    g_Th[65536 + c0 * 256 + d]          = __float2half(a02);
    g_Th[(c0 + 1) * 256 + d]            = __float2half(a10);
    g_Th[32768 + (c0 + 1) * 256 + d]    = __float2half(a11);
    g_Th[65536 + (c0 + 1) * 256 + d]    = __float2half(a12);
}

// ---------------- build u: half2 arithmetic, global tables (round-8 proven) ----------------
__global__ void k_build_u(const int* __restrict__ words,
                          const int* __restrict__ wic,
                          const float* __restrict__ word_emb,
                          const float* __restrict__ cb) {
    int w = blockIdx.x;            // 4096
    int t = threadIdx.x;           // 128
    __shared__ int codes[LCH];
    if (t < LCH) codes[t] = wic[w * LCH + t];
    __syncthreads();

    const float2* WE = (const float2*)word_emb;
    float2 wv = WE[(size_t)words[w] * 128 + t];
    __half2* UA = (__half2*)g_ua;  // row = 256 half2
    UA[(w + 1) * 256 + t] = __floats2half2_rn(wv.x, wv.y);

    const __half2* T0 = (const __half2*)g_Th;            // each table = 16384 half2
    const __half2* T1 = T0 + 16384;
    const __half2* T2 = T0 + 32768;
    float2 cbv = ((const float2*)cb)[t];
    __half2 bb = __floats2half2_rn(cbv.x, cbv.y);

    int c = codes[0];
    __half2 a0 = T0[c * 128 + t];
    __half2 a1 = T1[c * 128 + t];
    __half2 a2 = T2[c * 128 + t];
    __half2 accA = __hadd2(bb, a1);
    __half2 accB = __hadd2(bb, a0);
    __half2 m = __half2half2(__float2half(-60000.0f));
    (void)a2;
    #pragma unroll
    for (int s = 1; s < LCH; s++) {
        c = codes[s];
        a0 = T0[c * 128 + t];
        a1 = T1[c * 128 + t];
        a2 = T2[c * 128 + t];
        m = __hmax2(m, __hadd2(accA, a2));
        accA = __hadd2(accB, a1);
        accB = __hadd2(bb, a0);
    }
    m = __hmax2(m, accA);
    UA[(w + 1) * 256 + 128 + t] = m;

    __half2 z = __floats2half2_rn(0.f, 0.f);
    if (w == 0) { UA[t] = z; UA[128 + t] = z; }
    if (w == W_WORDS - 1) {
        size_t r = (size_t)(W_WORDS + 1) * 256;
        UA[r + t] = z; UA[r + 128 + t] = z;
    }
}

// ---------------- GEMM: single-product fp16, GK=64 (round-9 proven) ----------------
__global__ __launch_bounds__(256, 2) void k_gemm_mma() {
    extern __shared__ __align__(128) char smem[];
    uint32_t sb = smem_u32(smem);
    int tid = threadIdx.x;
    int lane = tid & 31, wq = tid >> 5;
    int wm = wq & 3, wn = wq >> 2;       // 4 m-warps x 2 n-warps; warp tile 32x32
    int n0 = blockIdx.x * GN;
    int w0 = blockIdx.y * GM;

    float acc[2][4][4];
    #pragma unroll
    for (int a = 0; a < 2; a++)
        #pragma unroll
        for (int f = 0; f < 4; f++)
            #pragma unroll
            for (int r = 0; r < 4; r++) acc[a][f][r] = 0.f;

    auto issue_stage = [&](int ck, int s) {
        int p0 = ck * GK;
        int kk = p0 >> 9, i0 = p0 & 511;
        uint32_t st = sb + s * STAGE_B;
        #pragma unroll
        for (int q = 0; q < 6; q++) {
            int idx = tid + q * 256;      // 0..1535
            if (idx < 1024) {             // A tile: 128 rows x 128B
                int r = idx >> 3, c8 = idx & 7;
                uint32_t dst = st + r * 128 + ((c8 ^ (r & 7)) << 4);
                const __half* src = g_ua + (size_t)(w0 + kk + r) * D2 + i0 + c8 * 8;
                cp16(dst, src);
            } else {                      // B tile: 64 rows x 128B
                int j = idx - 1024;
                int r = j >> 3, c8 = j & 7;
                uint32_t dst = st + A_TILE + r * 128 + ((c8 ^ (r & 7)) << 4);
                const __half* src = g_Bh + (size_t)(n0 + r) * KDIM + p0 + c8 * 8;
                cp16(dst, src);
            }
        }
        CP_COMMIT();
    };

    issue_stage(0, 0);
    issue_stage(1, 1);

    for (int ck = 0; ck < NK; ck++) {
        CP_WAIT1();
        __syncthreads();
        if (ck + 2 < NK) issue_stage(ck + 2, (ck + 2) % NSTAGE);
        else CP_COMMIT();

        uint32_t st = sb + (ck % NSTAGE) * STAGE_B;
        uint32_t aA = st, bH = st + A_TILE;
        #pragma unroll
        for (int ks = 0; ks < 4; ks++) {
            uint32_t ah[2][4];
            #pragma unroll
            for (int mf = 0; mf < 2; mf++) {
                int row = wm * 32 + mf * 16 + (lane & 7) + ((lane >> 3) & 1) * 8;
                int c = 2 * ks + (lane >> 4);
                uint32_t off = (uint32_t)(row * 128) + (uint32_t)((c ^ (row & 7)) << 4);
                ldmx4(ah[mf], aA + off);
            }
            #pragma unroll
            for (int bq = 0; bq < 2; bq++) {
                int row = wn * 32 + bq * 16 + (lane & 7) + ((lane >> 3) & 1) * 8;
                int c = 2 * ks + (lane >> 4);
                uint32_t off = (uint32_t)(row * 128) + (uint32_t)((c ^ (row & 7)) << 4);
                uint32_t bh[4];
                ldmx4(bh, bH + off);
                #pragma unroll
                for (int mf = 0; mf < 2; mf++) {
                    mma_f16(acc[mf][2 * bq],     ah[mf], bh[0], bh[2]);
                    mma_f16(acc[mf][2 * bq + 1], ah[mf], bh[1], bh[3]);
                }
            }
        }
    }

    // epilogue: column max over tile's 128 rows
    __syncthreads();
    float* red = (float*)smem;   // [4 wm][64 cols]
    #pragma unroll
    for (int f = 0; f < 4; f++) {
        float t0 = -1e30f, t1 = -1e30f;
        #pragma unroll
        for (int mf = 0; mf < 2; mf++) {
            t0 = fmaxf(t0, fmaxf(acc[mf][f][0], acc[mf][f][2]));
            t1 = fmaxf(t1, fmaxf(acc[mf][f][1], acc[mf][f][3]));
        }
        #pragma unroll
        for (int off = 4; off < 32; off <<= 1) {
            t0 = fmaxf(t0, __shfl_xor_sync(0xffffffffu, t0, off));
            t1 = fmaxf(t1, __shfl_xor_sync(0xffffffffu, t1, off));
        }
        if (lane < 4) {
            red[wm * 64 + wn * 32 + f * 8 + 2 * lane]     = t0;
            red[wm * 64 + wn * 32 + f * 8 + 2 * lane + 1] = t1;
        }
    }
    __syncthreads();
    if (tid < 64) {
        float m = red[tid];
        #pragma unroll
        for (int q = 1; q < 4; q++) m = fmaxf(m, red[q * 64 + tid]);
        unsigned u = __float_as_uint(m);
        unsigned key = (u & 0x80000000u) ? ~u : (u | 0x80000000u);
        atomicMax(&g_rkeys[n0 + tid], key);
    }
}

// ---------------- fused head: h = tanh(W1@(r+sb)+b1); out = W2@h + b2 ----------------
__global__ __launch_bounds__(1024, 1) void k_hout(const float* __restrict__ sb,
                                                  const float* __restrict__ w1,
                                                  const float* __restrict__ b1,
                                                  const float* __restrict__ w2,
                                                  const float* __restrict__ b2,
                                                  float* __restrict__ out) {
    __shared__ float rs[D2];
    __shared__ float hs[D4];
    int tid = threadIdx.x;         // 1024
    if (tid < D2) {
        unsigned key = g_rkeys[tid];
        unsigned u = (key & 0x80000000u) ? (key & 0x7FFFFFFFu) : ~key;
        rs[tid] = __uint_as_float(u) + sb[tid];
    }
    __syncthreads();
    int s = tid & 15, g = tid >> 4;     // 64 groups of 16
    #pragma unroll
    for (int it = 0; it < 16; it++) {
        int o = it * 64 + g;
        float accv = 0.f;
        for (int j = s; j < D2; j += 16) accv += w1[o * D2 + j] * rs[j];
        #pragma unroll
        for (int off = 8; off; off >>= 1) accv += __shfl_down_sync(0xffffffffu, accv, off, 16);
        if (s == 0) hs[o] = tanhf(accv + b1[o]);
    }
    __syncthreads();
    if (tid < 64) {
        int j = tid >> 5, lane = tid & 31;
        float accv = 0.f;
        for (int l = lane; l < D4; l += 32) accv += hs[l] * w2[j * D4 + l];
        #pragma unroll
        for (int off = 16; off; off >>= 1) accv += __shfl_down_sync(0xffffffffu, accv, off);
        if (lane == 0) out[j] = accv + b2[j];
    }
}

extern "C" void kernel_launch(void* const* d_in, const int* in_sizes, int n_in,
                              void* d_out, int out_size) {
    const int*   words       = (const int*)d_in[0];
    const int*   wic         = (const int*)d_in[1];
    const float* word_emb    = (const float*)d_in[2];
    const float* chr_emb     = (const float*)d_in[3];
    const float* conv_chr_w  = (const float*)d_in[4];
    const float* conv_chr_b  = (const float*)d_in[5];
    const float* conv_sent_w = (const float*)d_in[6];
    const float* conv_sent_b = (const float*)d_in[7];
    const float* w1          = (const float*)d_in[8];
    const float* b1          = (const float*)d_in[9];
    const float* w2          = (const float*)d_in[10];
    const float* b2          = (const float*)d_in[11];
    float* out = (float*)d_out;

    cudaFuncSetAttribute(k_gemm_mma, cudaFuncAttributeMaxDynamicSharedMemorySize, SMEM_DYN_GEMM);

    k_prep<<<1280, 256>>>(conv_chr_w, conv_sent_w);
    k_tables<<<64, 256>>>(chr_emb);
    k_build_u<<<W_WORDS, 128>>>(words, wic, word_emb, conv_chr_b);
    dim3 g3(D2 / GN, W_WORDS / GM);     // 8 x 32 = 256 CTAs
    k_gemm_mma<<<g3, 256, SMEM_DYN_GEMM>>>();
    k_hout<<<1, 1024>>>(conv_sent_b, w1, b1, w2, b2, out);
}

// round 11
// speedup vs baseline: 1.0684x; 1.0684x over previous
#include <cuda_runtime.h>
#include <cuda_bf16.h>
#include <cuda_fp16.h>
#include <cstdint>

// Sizes
#define W_WORDS 4096
#define LCH 32
#define D2 512
#define D4 1024
#define KDIM 1536   // 3*512

// GEMM tiling
#define GM 128
#define GN 64
#define GK 64
#define NK (KDIM / GK)            // 24
#define A_TILE (GM * GK * 2)      // 16384 B (fp16)
#define B_TILE (GN * GK * 2)      // 8192 B
#define STAGE_B (A_TILE + B_TILE) // 24576
#define NSTAGE 3
#define SMEM_DYN_GEMM (NSTAGE * STAGE_B)    // 73728

// ---------------- scratch ----------------
__device__ __align__(128) __half g_Th[3 * 128 * 256];        // fp16 lookup tables
__device__ __align__(128) __half g_ua[(W_WORDS + 2) * D2];   // u in fp16
__device__ __align__(128) __half g_Bh[D2 * KDIM];            // B fp16 [o][p] K-major
__device__ __align__(128) unsigned g_rkeys[D2];

// ---------------- helpers ----------------
__device__ __forceinline__ uint32_t smem_u32(const void* p) {
    uint32_t a;
    asm("{ .reg .u64 t; cvta.to.shared.u64 t, %1; cvt.u32.u64 %0, t; }" : "=r"(a) : "l"(p));
    return a;
}
__device__ __forceinline__ void ldmx4(uint32_t* r, uint32_t addr) {
    asm volatile("ldmatrix.sync.aligned.m8n8.x4.shared.b16 {%0,%1,%2,%3}, [%4];"
                 : "=r"(r[0]), "=r"(r[1]), "=r"(r[2]), "=r"(r[3]) : "r"(addr));
}
__device__ __forceinline__ void mma_f16(float* c, const uint32_t* a, uint32_t b0, uint32_t b1) {
    asm volatile("mma.sync.aligned.m16n8k16.row.col.f32.f16.f16.f32 "
                 "{%0,%1,%2,%3}, {%4,%5,%6,%7}, {%8,%9}, {%0,%1,%2,%3};"
                 : "+f"(c[0]), "+f"(c[1]), "+f"(c[2]), "+f"(c[3])
                 : "r"(a[0]), "r"(a[1]), "r"(a[2]), "r"(a[3]), "r"(b0), "r"(b1));
}
__device__ __forceinline__ void cp16(uint32_t dst, const void* src) {
    asm volatile("cp.async.cg.shared.global [%0], [%1], 16;" :: "r"(dst), "l"(src));
}
#define CP_COMMIT() asm volatile("cp.async.commit_group;" ::: "memory")
#define CP_WAIT1()  asm volatile("cp.async.wait_group 1;" ::: "memory")

// ---------------- merged prep: char tables (direct from wc) + B conversion ----------------
// blocks 0..63   : tables for 2 chars each (fp32 accumulate, fp16 store)
// blocks 64..575 : ws -> g_Bh K-major + rkeys init
__global__ void k_prep2(const float* __restrict__ wc,
                        const float* __restrict__ ws,
                        const float* __restrict__ chr_emb) {
    int b = blockIdx.x;
    if (b < 64) {
        __shared__ float ce[2][256];
        int d = threadIdx.x;       // 256
        int c0 = b * 2;
        ce[0][d] = chr_emb[c0 * 256 + d];
        ce[1][d] = chr_emb[(c0 + 1) * 256 + d];
        __syncthreads();
        // T_k[c][d] = sum_i ce[c][i] * wc[d*768 + i*3 + k]
        float a[2][3] = {{0.f, 0.f, 0.f}, {0.f, 0.f, 0.f}};
        const float4* row = (const float4*)(wc + (size_t)d * 768);
        #pragma unroll 8
        for (int i4 = 0; i4 < 64; i4++) {
            float4 x0 = row[3 * i4];
            float4 x1 = row[3 * i4 + 1];
            float4 x2 = row[3 * i4 + 2];
            int ib = i4 * 4;
            #pragma unroll
            for (int q = 0; q < 2; q++) {
                float e0 = ce[q][ib], e1 = ce[q][ib + 1], e2 = ce[q][ib + 2], e3 = ce[q][ib + 3];
                a[q][0] += e0 * x0.x + e1 * x0.w + e2 * x1.z + e3 * x2.y;
                a[q][1] += e0 * x0.y + e1 * x1.x + e2 * x1.w + e3 * x2.z;
                a[q][2] += e0 * x0.z + e1 * x1.y + e2 * x2.x + e3 * x2.w;
            }
        }
        #pragma unroll
        for (int q = 0; q < 2; q++) {
            g_Th[(c0 + q) * 256 + d]         = __float2half(a[q][0]);
            g_Th[32768 + (c0 + q) * 256 + d] = __float2half(a[q][1]);
            g_Th[65536 + (c0 + q) * 256 + d] = __float2half(a[q][2]);
        }
    } else {
        int o = b - 64;            // 512
        for (int p = threadIdx.x; p < KDIM; p += 256) {
            int kk = p >> 9, i = p & 511;
            g_Bh[o * KDIM + p] = __float2half(ws[o * KDIM + i * 3 + kk]);
        }
        if (o == 0) { g_rkeys[threadIdx.x] = 0u; g_rkeys[threadIdx.x + 256] = 0u; }
    }
}

// ---------------- build u: half2 arithmetic, global tables (proven) ----------------
__global__ void k_build_u(const int* __restrict__ words,
                          const int* __restrict__ wic,
                          const float* __restrict__ word_emb,
                          const float* __restrict__ cb) {
    int w = blockIdx.x;            // 4096
    int t = threadIdx.x;           // 128
    __shared__ int codes[LCH];
    if (t < LCH) codes[t] = wic[w * LCH + t];
    __syncthreads();

    const float2* WE = (const float2*)word_emb;
    float2 wv = WE[(size_t)words[w] * 128 + t];
    __half2* UA = (__half2*)g_ua;  // row = 256 half2
    UA[(w + 1) * 256 + t] = __floats2half2_rn(wv.x, wv.y);

    const __half2* T0 = (const __half2*)g_Th;            // each table = 16384 half2
    const __half2* T1 = T0 + 16384;
    const __half2* T2 = T0 + 32768;
    float2 cbv = ((const float2*)cb)[t];
    __half2 bb = __floats2half2_rn(cbv.x, cbv.y);

    int c = codes[0];
    __half2 a0 = T0[c * 128 + t];
    __half2 a1 = T1[c * 128 + t];
    __half2 a2 = T2[c * 128 + t];
    __half2 accA = __hadd2(bb, a1);
    __half2 accB = __hadd2(bb, a0);
    __half2 m = __half2half2(__float2half(-60000.0f));
    (void)a2;
    #pragma unroll
    for (int s = 1; s < LCH; s++) {
        c = codes[s];
        a0 = T0[c * 128 + t];
        a1 = T1[c * 128 + t];
        a2 = T2[c * 128 + t];
        m = __hmax2(m, __hadd2(accA, a2));
        accA = __hadd2(accB, a1);
        accB = __hadd2(bb, a0);
    }
    m = __hmax2(m, accA);
    UA[(w + 1) * 256 + 128 + t] = m;

    __half2 z = __floats2half2_rn(0.f, 0.f);
    if (w == 0) { UA[t] = z; UA[128 + t] = z; }
    if (w == W_WORDS - 1) {
        size_t r = (size_t)(W_WORDS + 1) * 256;
        UA[r + t] = z; UA[r + 128 + t] = z;
    }
}

// ---------------- GEMM: single-product fp16, GK=64 (proven 26.5us) ----------------
__global__ __launch_bounds__(256, 2) void k_gemm_mma() {
    extern __shared__ __align__(128) char smem[];
    uint32_t sb = smem_u32(smem);
    int tid = threadIdx.x;
    int lane = tid & 31, wq = tid >> 5;
    int wm = wq & 3, wn = wq >> 2;       // 4 m-warps x 2 n-warps; warp tile 32x32
    int n0 = blockIdx.x * GN;
    int w0 = blockIdx.y * GM;

    float acc[2][4][4];
    #pragma unroll
    for (int a = 0; a < 2; a++)
        #pragma unroll
        for (int f = 0; f < 4; f++)
            #pragma unroll
            for (int r = 0; r < 4; r++) acc[a][f][r] = 0.f;

    auto issue_stage = [&](int ck, int s) {
        int p0 = ck * GK;
        int kk = p0 >> 9, i0 = p0 & 511;
        uint32_t st = sb + s * STAGE_B;
        #pragma unroll
        for (int q = 0; q < 6; q++) {
            int idx = tid + q * 256;      // 0..1535
            if (idx < 1024) {             // A tile: 128 rows x 128B
                int r = idx >> 3, c8 = idx & 7;
                uint32_t dst = st + r * 128 + ((c8 ^ (r & 7)) << 4);
                const __half* src = g_ua + (size_t)(w0 + kk + r) * D2 + i0 + c8 * 8;
                cp16(dst, src);
            } else {                      // B tile: 64 rows x 128B
                int j = idx - 1024;
                int r = j >> 3, c8 = j & 7;
                uint32_t dst = st + A_TILE + r * 128 + ((c8 ^ (r & 7)) << 4);
                const __half* src = g_Bh + (size_t)(n0 + r) * KDIM + p0 + c8 * 8;
                cp16(dst, src);
            }
        }
        CP_COMMIT();
    };

    issue_stage(0, 0);
    issue_stage(1, 1);

    for (int ck = 0; ck < NK; ck++) {
        CP_WAIT1();
        __syncthreads();
        if (ck + 2 < NK) issue_stage(ck + 2, (ck + 2) % NSTAGE);
        else CP_COMMIT();

        uint32_t st = sb + (ck % NSTAGE) * STAGE_B;
        uint32_t aA = st, bH = st + A_TILE;
        #pragma unroll
        for (int ks = 0; ks < 4; ks++) {
            uint32_t ah[2][4];
            #pragma unroll
            for (int mf = 0; mf < 2; mf++) {
                int row = wm * 32 + mf * 16 + (lane & 7) + ((lane >> 3) & 1) * 8;
                int c = 2 * ks + (lane >> 4);
                uint32_t off = (uint32_t)(row * 128) + (uint32_t)((c ^ (row & 7)) << 4);
                ldmx4(ah[mf], aA + off);
            }
            #pragma unroll
            for (int bq = 0; bq < 2; bq++) {
                int row = wn * 32 + bq * 16 + (lane & 7) + ((lane >> 3) & 1) * 8;
                int c = 2 * ks + (lane >> 4);
                uint32_t off = (uint32_t)(row * 128) + (uint32_t)((c ^ (row & 7)) << 4);
                uint32_t bh[4];
                ldmx4(bh, bH + off);
                #pragma unroll
                for (int mf = 0; mf < 2; mf++) {
                    mma_f16(acc[mf][2 * bq],     ah[mf], bh[0], bh[2]);
                    mma_f16(acc[mf][2 * bq + 1], ah[mf], bh[1], bh[3]);
                }
            }
        }
    }

    // epilogue: column max over tile's 128 rows
    __syncthreads();
    float* red = (float*)smem;   // [4 wm][64 cols]
    #pragma unroll
    for (int f = 0; f < 4; f++) {
        float t0 = -1e30f, t1 = -1e30f;
        #pragma unroll
        for (int mf = 0; mf < 2; mf++) {
            t0 = fmaxf(t0, fmaxf(acc[mf][f][0], acc[mf][f][2]));
            t1 = fmaxf(t1, fmaxf(acc[mf][f][1], acc[mf][f][3]));
        }
        #pragma unroll
        for (int off = 4; off < 32; off <<= 1) {
            t0 = fmaxf(t0, __shfl_xor_sync(0xffffffffu, t0, off));
            t1 = fmaxf(t1, __shfl_xor_sync(0xffffffffu, t1, off));
        }
        if (lane < 4) {
            red[wm * 64 + wn * 32 + f * 8 + 2 * lane]     = t0;
            red[wm * 64 + wn * 32 + f * 8 + 2 * lane + 1] = t1;
        }
    }
    __syncthreads();
    if (tid < 64) {
        float m = red[tid];
        #pragma unroll
        for (int q = 1; q < 4; q++) m = fmaxf(m, red[q * 64 + tid]);
        unsigned u = __float_as_uint(m);
        unsigned key = (u & 0x80000000u) ? ~u : (u | 0x80000000u);
        atomicMax(&g_rkeys[n0 + tid], key);
    }
}

// ---------------- fused head: h = tanh(W1@(r+sb)+b1); out = W2@h + b2 ----------------
__global__ __launch_bounds__(1024, 1) void k_hout(const float* __restrict__ sb,
                                                  const float* __restrict__ w1,
                                                  const float* __restrict__ b1,
                                                  const float* __restrict__ w2,
                                                  const float* __restrict__ b2,
                                                  float* __restrict__ out) {
    __shared__ float rs[D2];
    __shared__ float hs[D4];
    int tid = threadIdx.x;         // 1024
    if (tid < D2) {
        unsigned key = g_rkeys[tid];
        unsigned u = (key & 0x80000000u) ? (key & 0x7FFFFFFFu) : ~key;
        rs[tid] = __uint_as_float(u) + sb[tid];
    }
    __syncthreads();
    int s = tid & 15, g = tid >> 4;     // 64 groups of 16
    #pragma unroll
    for (int it = 0; it < 16; it++) {
        int o = it * 64 + g;
        float accv = 0.f;
        for (int j = s; j < D2; j += 16) accv += w1[o * D2 + j] * rs[j];
        #pragma unroll
        for (int off = 8; off; off >>= 1) accv += __shfl_down_sync(0xffffffffu, accv, off, 16);
        if (s == 0) hs[o] = tanhf(accv + b1[o]);
    }
    __syncthreads();
    if (tid < 64) {
        int j = tid >> 5, lane = tid & 31;
        float accv = 0.f;
        for (int l = lane; l < D4; l += 32) accv += hs[l] * w2[j * D4 + l];
        #pragma unroll
        for (int off = 16; off; off >>= 1) accv += __shfl_down_sync(0xffffffffu, accv, off);
        if (lane == 0) out[j] = accv + b2[j];
    }
}

extern "C" void kernel_launch(void* const* d_in, const int* in_sizes, int n_in,
                              void* d_out, int out_size) {
    const int*   words       = (const int*)d_in[0];
    const int*   wic         = (const int*)d_in[1];
    const float* word_emb    = (const float*)d_in[2];
    const float* chr_emb     = (const float*)d_in[3];
    const float* conv_chr_w  = (const float*)d_in[4];
    const float* conv_chr_b  = (const float*)d_in[5];
    const float* conv_sent_w = (const float*)d_in[6];
    const float* conv_sent_b = (const float*)d_in[7];
    const float* w1          = (const float*)d_in[8];
    const float* b1          = (const float*)d_in[9];
    const float* w2          = (const float*)d_in[10];
    const float* b2          = (const float*)d_in[11];
    float* out = (float*)d_out;

    cudaFuncSetAttribute(k_gemm_mma, cudaFuncAttributeMaxDynamicSharedMemorySize, SMEM_DYN_GEMM);

    k_prep2<<<576, 256>>>(conv_chr_w, conv_sent_w, chr_emb);
    k_build_u<<<W_WORDS, 128>>>(words, wic, word_emb, conv_chr_b);
    dim3 g3(D2 / GN, W_WORDS / GM);     // 8 x 32 = 256 CTAs
    k_gemm_mma<<<g3, 256, SMEM_DYN_GEMM>>>();
    k_hout<<<1, 1024>>>(conv_sent_b, w1, b1, w2, b2, out);
}

// round 12
// speedup vs baseline: 1.4485x; 1.3558x over previous
#include <cuda_runtime.h>
#include <cuda_bf16.h>
#include <cuda_fp16.h>
#include <cstdint>

// Sizes
#define W_WORDS 4096
#define LCH 32
#define D2 512
#define D4 1024
#define KDIM 1536   // 3*512

// GEMM tiling
#define GM 128
#define GN 64
#define GK 64
#define NK (KDIM / GK)            // 24
#define A_TILE (GM * GK * 2)      // 16384 B (fp16)
#define B_TILE (GN * GK * 2)      // 8192 B
#define STAGE_B (A_TILE + B_TILE) // 24576
#define NSTAGE 3
#define SMEM_DYN_GEMM (NSTAGE * STAGE_B)    // 73728

// ---------------- scratch ----------------
__device__ __align__(128) __half g_Th[3 * 128 * 256];        // fp16 lookup tables
__device__ __align__(128) __half g_ua[(W_WORDS + 2) * D2];   // u in fp16
__device__ __align__(128) __half g_Bh[D2 * KDIM];            // B fp16 [o][p] K-major
__device__ __align__(128) unsigned g_rkeys[D2];
__device__ __align__(128) float  g_h[D4];

// ---------------- helpers ----------------
__device__ __forceinline__ uint32_t smem_u32(const void* p) {
    uint32_t a;
    asm("{ .reg .u64 t; cvta.to.shared.u64 t, %1; cvt.u32.u64 %0, t; }" : "=r"(a) : "l"(p));
    return a;
}
__device__ __forceinline__ void ldmx4(uint32_t* r, uint32_t addr) {
    asm volatile("ldmatrix.sync.aligned.m8n8.x4.shared.b16 {%0,%1,%2,%3}, [%4];"
                 : "=r"(r[0]), "=r"(r[1]), "=r"(r[2]), "=r"(r[3]) : "r"(addr));
}
__device__ __forceinline__ void mma_f16(float* c, const uint32_t* a, uint32_t b0, uint32_t b1) {
    asm volatile("mma.sync.aligned.m16n8k16.row.col.f32.f16.f16.f32 "
                 "{%0,%1,%2,%3}, {%4,%5,%6,%7}, {%8,%9}, {%0,%1,%2,%3};"
                 : "+f"(c[0]), "+f"(c[1]), "+f"(c[2]), "+f"(c[3])
                 : "r"(a[0]), "r"(a[1]), "r"(a[2]), "r"(a[3]), "r"(b0), "r"(b1));
}
__device__ __forceinline__ void cp16(uint32_t dst, const void* src) {
    asm volatile("cp.async.cg.shared.global [%0], [%1], 16;" :: "r"(dst), "l"(src));
}
#define CP_COMMIT() asm volatile("cp.async.commit_group;" ::: "memory")
#define CP_WAIT1()  asm volatile("cp.async.wait_group 1;" ::: "memory")

// ---------------- merged prep: char tables (direct from wc) + B conversion ----------------
// blocks 0..63   : tables for 2 chars each (fp32 accumulate, fp16 store)
// blocks 64..575 : ws -> g_Bh K-major + rkeys init
__global__ void k_prep2(const float* __restrict__ wc,
                        const float* __restrict__ ws,
                        const float* __restrict__ chr_emb) {
    int b = blockIdx.x;
    if (b < 64) {
        __shared__ float ce[2][256];
        int d = threadIdx.x;       // 256
        int c0 = b * 2;
        ce[0][d] = chr_emb[c0 * 256 + d];
        ce[1][d] = chr_emb[(c0 + 1) * 256 + d];
        __syncthreads();
        // T_k[c][d] = sum_i ce[c][i] * wc[d*768 + i*3 + k]
        float a[2][3] = {{0.f, 0.f, 0.f}, {0.f, 0.f, 0.f}};
        const float4* row = (const float4*)(wc + (size_t)d * 768);
        #pragma unroll 8
        for (int i4 = 0; i4 < 64; i4++) {
            float4 x0 = row[3 * i4];
            float4 x1 = row[3 * i4 + 1];
            float4 x2 = row[3 * i4 + 2];
            int ib = i4 * 4;
            #pragma unroll
            for (int q = 0; q < 2; q++) {
                float e0 = ce[q][ib], e1 = ce[q][ib + 1], e2 = ce[q][ib + 2], e3 = ce[q][ib + 3];
                a[q][0] += e0 * x0.x + e1 * x0.w + e2 * x1.z + e3 * x2.y;
                a[q][1] += e0 * x0.y + e1 * x1.x + e2 * x1.w + e3 * x2.z;
                a[q][2] += e0 * x0.z + e1 * x1.y + e2 * x2.x + e3 * x2.w;
            }
        }
        #pragma unroll
        for (int q = 0; q < 2; q++) {
            g_Th[(c0 + q) * 256 + d]         = __float2half(a[q][0]);
            g_Th[32768 + (c0 + q) * 256 + d] = __float2half(a[q][1]);
            g_Th[65536 + (c0 + q) * 256 + d] = __float2half(a[q][2]);
        }
    } else {
        int o = b - 64;            // 512
        for (int p = threadIdx.x; p < KDIM; p += 256) {
            int kk = p >> 9, i = p & 511;
            g_Bh[o * KDIM + p] = __float2half(ws[o * KDIM + i * 3 + kk]);
        }
        if (o == 0) { g_rkeys[threadIdx.x] = 0u; g_rkeys[threadIdx.x + 256] = 0u; }
    }
}

// ---------------- build u: half2 arithmetic, global tables (proven) ----------------
__global__ void k_build_u(const int* __restrict__ words,
                          const int* __restrict__ wic,
                          const float* __restrict__ word_emb,
                          const float* __restrict__ cb) {
    int w = blockIdx.x;            // 4096
    int t = threadIdx.x;           // 128
    __shared__ int codes[LCH];
    if (t < LCH) codes[t] = wic[w * LCH + t];
    __syncthreads();

    const float2* WE = (const float2*)word_emb;
    float2 wv = WE[(size_t)words[w] * 128 + t];
    __half2* UA = (__half2*)g_ua;  // row = 256 half2
    UA[(w + 1) * 256 + t] = __floats2half2_rn(wv.x, wv.y);

    const __half2* T0 = (const __half2*)g_Th;            // each table = 16384 half2
    const __half2* T1 = T0 + 16384;
    const __half2* T2 = T0 + 32768;
    float2 cbv = ((const float2*)cb)[t];
    __half2 bb = __floats2half2_rn(cbv.x, cbv.y);

    int c = codes[0];
    __half2 a0 = T0[c * 128 + t];
    __half2 a1 = T1[c * 128 + t];
    __half2 a2 = T2[c * 128 + t];
    __half2 accA = __hadd2(bb, a1);
    __half2 accB = __hadd2(bb, a0);
    __half2 m = __half2half2(__float2half(-60000.0f));
    (void)a2;
    #pragma unroll
    for (int s = 1; s < LCH; s++) {
        c = codes[s];
        a0 = T0[c * 128 + t];
        a1 = T1[c * 128 + t];
        a2 = T2[c * 128 + t];
        m = __hmax2(m, __hadd2(accA, a2));
        accA = __hadd2(accB, a1);
        accB = __hadd2(bb, a0);
    }
    m = __hmax2(m, accA);
    UA[(w + 1) * 256 + 128 + t] = m;

    __half2 z = __floats2half2_rn(0.f, 0.f);
    if (w == 0) { UA[t] = z; UA[128 + t] = z; }
    if (w == W_WORDS - 1) {
        size_t r = (size_t)(W_WORDS + 1) * 256;
        UA[r + t] = z; UA[r + 128 + t] = z;
    }
}

// ---------------- GEMM: single-product fp16, GK=64 (proven 26.5us) ----------------
__global__ __launch_bounds__(256, 2) void k_gemm_mma() {
    extern __shared__ __align__(128) char smem[];
    uint32_t sb = smem_u32(smem);
    int tid = threadIdx.x;
    int lane = tid & 31, wq = tid >> 5;
    int wm = wq & 3, wn = wq >> 2;       // 4 m-warps x 2 n-warps; warp tile 32x32
    int n0 = blockIdx.x * GN;
    int w0 = blockIdx.y * GM;

    float acc[2][4][4];
    #pragma unroll
    for (int a = 0; a < 2; a++)
        #pragma unroll
        for (int f = 0; f < 4; f++)
            #pragma unroll
            for (int r = 0; r < 4; r++) acc[a][f][r] = 0.f;

    auto issue_stage = [&](int ck, int s) {
        int p0 = ck * GK;
        int kk = p0 >> 9, i0 = p0 & 511;
        uint32_t st = sb + s * STAGE_B;
        #pragma unroll
        for (int q = 0; q < 6; q++) {
            int idx = tid + q * 256;      // 0..1535
            if (idx < 1024) {             // A tile: 128 rows x 128B
                int r = idx >> 3, c8 = idx & 7;
                uint32_t dst = st + r * 128 + ((c8 ^ (r & 7)) << 4);
                const __half* src = g_ua + (size_t)(w0 + kk + r) * D2 + i0 + c8 * 8;
                cp16(dst, src);
            } else {                      // B tile: 64 rows x 128B
                int j = idx - 1024;
                int r = j >> 3, c8 = j & 7;
                uint32_t dst = st + A_TILE + r * 128 + ((c8 ^ (r & 7)) << 4);
                const __half* src = g_Bh + (size_t)(n0 + r) * KDIM + p0 + c8 * 8;
                cp16(dst, src);
            }
        }
        CP_COMMIT();
    };

    issue_stage(0, 0);
    issue_stage(1, 1);

    for (int ck = 0; ck < NK; ck++) {
        CP_WAIT1();
        __syncthreads();
        if (ck + 2 < NK) issue_stage(ck + 2, (ck + 2) % NSTAGE);
        else CP_COMMIT();

        uint32_t st = sb + (ck % NSTAGE) * STAGE_B;
        uint32_t aA = st, bH = st + A_TILE;
        #pragma unroll
        for (int ks = 0; ks < 4; ks++) {
            uint32_t ah[2][4];
            #pragma unroll
            for (int mf = 0; mf < 2; mf++) {
                int row = wm * 32 + mf * 16 + (lane & 7) + ((lane >> 3) & 1) * 8;
                int c = 2 * ks + (lane >> 4);
                uint32_t off = (uint32_t)(row * 128) + (uint32_t)((c ^ (row & 7)) << 4);
                ldmx4(ah[mf], aA + off);
            }
            #pragma unroll
            for (int bq = 0; bq < 2; bq++) {
                int row = wn * 32 + bq * 16 + (lane & 7) + ((lane >> 3) & 1) * 8;
                int c = 2 * ks + (lane >> 4);
                uint32_t off = (uint32_t)(row * 128) + (uint32_t)((c ^ (row & 7)) << 4);
                uint32_t bh[4];
                ldmx4(bh, bH + off);
                #pragma unroll
                for (int mf = 0; mf < 2; mf++) {
                    mma_f16(acc[mf][2 * bq],     ah[mf], bh[0], bh[2]);
                    mma_f16(acc[mf][2 * bq + 1], ah[mf], bh[1], bh[3]);
                }
            }
        }
    }

    // epilogue: column max over tile's 128 rows
    __syncthreads();
    float* red = (float*)smem;   // [4 wm][64 cols]
    #pragma unroll
    for (int f = 0; f < 4; f++) {
        float t0 = -1e30f, t1 = -1e30f;
        #pragma unroll
        for (int mf = 0; mf < 2; mf++) {
            t0 = fmaxf(t0, fmaxf(acc[mf][f][0], acc[mf][f][2]));
            t1 = fmaxf(t1, fmaxf(acc[mf][f][1], acc[mf][f][3]));
        }
        #pragma unroll
        for (int off = 4; off < 32; off <<= 1) {
            t0 = fmaxf(t0, __shfl_xor_sync(0xffffffffu, t0, off));
            t1 = fmaxf(t1, __shfl_xor_sync(0xffffffffu, t1, off));
        }
        if (lane < 4) {
            red[wm * 64 + wn * 32 + f * 8 + 2 * lane]     = t0;
            red[wm * 64 + wn * 32 + f * 8 + 2 * lane + 1] = t1;
        }
    }
    __syncthreads();
    if (tid < 64) {
        float m = red[tid];
        #pragma unroll
        for (int q = 1; q < 4; q++) m = fmaxf(m, red[q * 64 + tid]);
        unsigned u = __float_as_uint(m);
        unsigned key = (u & 0x80000000u) ? ~u : (u | 0x80000000u);
        atomicMax(&g_rkeys[n0 + tid], key);
    }
}

// ---------------- head: h = tanh(W1@(r+sb)+b1), 64 CTAs (full-chip W1 bandwidth) ----------------
__global__ void k_h(const float* __restrict__ sb,
                    const float* __restrict__ w1,
                    const float* __restrict__ b1) {
    __shared__ float rs[D2];
    int tid = threadIdx.x;         // 256
    for (int j = tid; j < D2; j += 256) {
        unsigned key = g_rkeys[j];
        unsigned u = (key & 0x80000000u) ? (key & 0x7FFFFFFFu) : ~key;
        rs[j] = __uint_as_float(u) + sb[j];
    }
    __syncthreads();
    int g = tid >> 4, s = tid & 15;
    int o = blockIdx.x * 16 + g;   // 64 blocks x 16 outputs
    float accv = 0.f;
    for (int j = s; j < D2; j += 16) accv += w1[o * D2 + j] * rs[j];
    #pragma unroll
    for (int off = 8; off; off >>= 1) accv += __shfl_down_sync(0xffffffffu, accv, off, 16);
    if (s == 0) g_h[o] = tanhf(accv + b1[o]);
}

__global__ void k_out(const float* __restrict__ w2,
                      const float* __restrict__ b2,
                      float* __restrict__ out) {
    int j = threadIdx.x >> 5, lane = threadIdx.x & 31;
    float accv = 0.f;
    for (int l = lane; l < D4; l += 32) accv += g_h[l] * w2[j * D4 + l];
    #pragma unroll
    for (int off = 16; off; off >>= 1) accv += __shfl_down_sync(0xffffffffu, accv, off);
    if (lane == 0) out[j] = accv + b2[j];
}

extern "C" void kernel_launch(void* const* d_in, const int* in_sizes, int n_in,
                              void* d_out, int out_size) {
    const int*   words       = (const int*)d_in[0];
    const int*   wic         = (const int*)d_in[1];
    const float* word_emb    = (const float*)d_in[2];
    const float* chr_emb     = (const float*)d_in[3];
    const float* conv_chr_w  = (const float*)d_in[4];
    const float* conv_chr_b  = (const float*)d_in[5];
    const float* conv_sent_w = (const float*)d_in[6];
    const float* conv_sent_b = (const float*)d_in[7];
    const float* w1          = (const float*)d_in[8];
    const float* b1          = (const float*)d_in[9];
    const float* w2          = (const float*)d_in[10];
    const float* b2          = (const float*)d_in[11];
    float* out = (float*)d_out;

    cudaFuncSetAttribute(k_gemm_mma, cudaFuncAttributeMaxDynamicSharedMemorySize, SMEM_DYN_GEMM);

    k_prep2<<<576, 256>>>(conv_chr_w, conv_sent_w, chr_emb);
    k_build_u<<<W_WORDS, 128>>>(words, wic, word_emb, conv_chr_b);
    dim3 g3(D2 / GN, W_WORDS / GM);     // 8 x 32 = 256 CTAs
    k_gemm_mma<<<g3, 256, SMEM_DYN_GEMM>>>();
    k_h<<<64, 256>>>(conv_sent_b, w1, b1);
    k_out<<<1, 64>>>(w2, b2, out);
}

// round 13
// speedup vs baseline: 1.4581x; 1.0066x over previous
#include <cuda_runtime.h>
#include <cuda_bf16.h>
#include <cuda_fp16.h>
#include <cstdint>

// Sizes
#define W_WORDS 4096
#define LCH 32
#define D2 512
#define D4 1024
#define KDIM 1536   // 3*512

// GEMM tiling
#define GM 128
#define GN 64
#define GK 64
#define NK (KDIM / GK)            // 24
#define A_TILE (GM * GK * 2)      // 16384 B (fp16)
#define B_TILE (GN * GK * 2)      // 8192 B
#define STAGE_B (A_TILE + B_TILE) // 24576
#define NSTAGE 4
#define SMEM_DYN_GEMM (NSTAGE * STAGE_B)    // 98304

// ---------------- scratch ----------------
__device__ __align__(128) __half g_Th[3 * 128 * 256];        // fp16 lookup tables
__device__ __align__(128) __half g_ua[(W_WORDS + 2) * D2];   // u in fp16
__device__ __align__(128) __half g_Bh[D2 * KDIM];            // B fp16 [o][p] K-major
__device__ __align__(128) unsigned g_rkeys[D2];
__device__ __align__(128) float  g_h[D4];

// ---------------- helpers ----------------
__device__ __forceinline__ uint32_t smem_u32(const void* p) {
    uint32_t a;
    asm("{ .reg .u64 t; cvta.to.shared.u64 t, %1; cvt.u32.u64 %0, t; }" : "=r"(a) : "l"(p));
    return a;
}
__device__ __forceinline__ void ldmx4(uint32_t* r, uint32_t addr) {
    asm volatile("ldmatrix.sync.aligned.m8n8.x4.shared.b16 {%0,%1,%2,%3}, [%4];"
                 : "=r"(r[0]), "=r"(r[1]), "=r"(r[2]), "=r"(r[3]) : "r"(addr));
}
__device__ __forceinline__ void mma_f16(float* c, const uint32_t* a, uint32_t b0, uint32_t b1) {
    asm volatile("mma.sync.aligned.m16n8k16.row.col.f32.f16.f16.f32 "
                 "{%0,%1,%2,%3}, {%4,%5,%6,%7}, {%8,%9}, {%0,%1,%2,%3};"
                 : "+f"(c[0]), "+f"(c[1]), "+f"(c[2]), "+f"(c[3])
                 : "r"(a[0]), "r"(a[1]), "r"(a[2]), "r"(a[3]), "r"(b0), "r"(b1));
}
__device__ __forceinline__ void cp16(uint32_t dst, const void* src) {
    asm volatile("cp.async.cg.shared.global [%0], [%1], 16;" :: "r"(dst), "l"(src));
}
#define CP_COMMIT() asm volatile("cp.async.commit_group;" ::: "memory")
#define CP_WAIT2()  asm volatile("cp.async.wait_group 2;" ::: "memory")

// ---------------- merged prep: char tables (direct from wc) + B conversion ----------------
__global__ void k_prep2(const float* __restrict__ wc,
                        const float* __restrict__ ws,
                        const float* __restrict__ chr_emb) {
    int b = blockIdx.x;
    if (b < 64) {
        __shared__ float ce[2][256];
        int d = threadIdx.x;       // 256
        int c0 = b * 2;
        ce[0][d] = chr_emb[c0 * 256 + d];
        ce[1][d] = chr_emb[(c0 + 1) * 256 + d];
        __syncthreads();
        float a[2][3] = {{0.f, 0.f, 0.f}, {0.f, 0.f, 0.f}};
        const float4* row = (const float4*)(wc + (size_t)d * 768);
        #pragma unroll 8
        for (int i4 = 0; i4 < 64; i4++) {
            float4 x0 = row[3 * i4];
            float4 x1 = row[3 * i4 + 1];
            float4 x2 = row[3 * i4 + 2];
            int ib = i4 * 4;
            #pragma unroll
            for (int q = 0; q < 2; q++) {
                float e0 = ce[q][ib], e1 = ce[q][ib + 1], e2 = ce[q][ib + 2], e3 = ce[q][ib + 3];
                a[q][0] += e0 * x0.x + e1 * x0.w + e2 * x1.z + e3 * x2.y;
                a[q][1] += e0 * x0.y + e1 * x1.x + e2 * x1.w + e3 * x2.z;
                a[q][2] += e0 * x0.z + e1 * x1.y + e2 * x2.x + e3 * x2.w;
            }
        }
        #pragma unroll
        for (int q = 0; q < 2; q++) {
            g_Th[(c0 + q) * 256 + d]         = __float2half(a[q][0]);
            g_Th[32768 + (c0 + q) * 256 + d] = __float2half(a[q][1]);
            g_Th[65536 + (c0 + q) * 256 + d] = __float2half(a[q][2]);
        }
    } else {
        int o = b - 64;            // 512
        for (int p = threadIdx.x; p < KDIM; p += 256) {
            int kk = p >> 9, i = p & 511;
            g_Bh[o * KDIM + p] = __float2half(ws[o * KDIM + i * 3 + kk]);
        }
        if (o == 0) { g_rkeys[threadIdx.x] = 0u; g_rkeys[threadIdx.x + 256] = 0u; }
    }
}

// ---------------- build u: half2 arithmetic, global tables (proven) ----------------
__global__ void k_build_u(const int* __restrict__ words,
                          const int* __restrict__ wic,
                          const float* __restrict__ word_emb,
                          const float* __restrict__ cb) {
    int w = blockIdx.x;            // 4096
    int t = threadIdx.x;           // 128
    __shared__ int codes[LCH];
    if (t < LCH) codes[t] = wic[w * LCH + t];
    __syncthreads();

    const float2* WE = (const float2*)word_emb;
    float2 wv = WE[(size_t)words[w] * 128 + t];
    __half2* UA = (__half2*)g_ua;  // row = 256 half2
    UA[(w + 1) * 256 + t] = __floats2half2_rn(wv.x, wv.y);

    const __half2* T0 = (const __half2*)g_Th;            // each table = 16384 half2
    const __half2* T1 = T0 + 16384;
    const __half2* T2 = T0 + 32768;
    float2 cbv = ((const float2*)cb)[t];
    __half2 bb = __floats2half2_rn(cbv.x, cbv.y);

    int c = codes[0];
    __half2 a0 = T0[c * 128 + t];
    __half2 a1 = T1[c * 128 + t];
    __half2 a2 = T2[c * 128 + t];
    __half2 accA = __hadd2(bb, a1);
    __half2 accB = __hadd2(bb, a0);
    __half2 m = __half2half2(__float2half(-60000.0f));
    (void)a2;
    #pragma unroll
    for (int s = 1; s < LCH; s++) {
        c = codes[s];
        a0 = T0[c * 128 + t];
        a1 = T1[c * 128 + t];
        a2 = T2[c * 128 + t];
        m = __hmax2(m, __hadd2(accA, a2));
        accA = __hadd2(accB, a1);
        accB = __hadd2(bb, a0);
    }
    m = __hmax2(m, accA);
    UA[(w + 1) * 256 + 128 + t] = m;

    __half2 z = __floats2half2_rn(0.f, 0.f);
    if (w == 0) { UA[t] = z; UA[128 + t] = z; }
    if (w == W_WORDS - 1) {
        size_t r = (size_t)(W_WORDS + 1) * 256;
        UA[r + t] = z; UA[r + 128 + t] = z;
    }
}

// ---------------- GEMM: single-product fp16, GK=64, 4-stage pipeline ----------------
__global__ __launch_bounds__(256, 2) void k_gemm_mma() {
    extern __shared__ __align__(128) char smem[];
    uint32_t sb = smem_u32(smem);
    int tid = threadIdx.x;
    int lane = tid & 31, wq = tid >> 5;
    int wm = wq & 3, wn = wq >> 2;       // 4 m-warps x 2 n-warps; warp tile 32x32
    int n0 = blockIdx.x * GN;
    int w0 = blockIdx.y * GM;

    float acc[2][4][4];
    #pragma unroll
    for (int a = 0; a < 2; a++)
        #pragma unroll
        for (int f = 0; f < 4; f++)
            #pragma unroll
            for (int r = 0; r < 4; r++) acc[a][f][r] = 0.f;

    auto issue_stage = [&](int ck, int s) {
        int p0 = ck * GK;
        int kk = p0 >> 9, i0 = p0 & 511;
        uint32_t st = sb + s * STAGE_B;
        #pragma unroll
        for (int q = 0; q < 6; q++) {
            int idx = tid + q * 256;      // 0..1535
            if (idx < 1024) {             // A tile: 128 rows x 128B
                int r = idx >> 3, c8 = idx & 7;
                uint32_t dst = st + r * 128 + ((c8 ^ (r & 7)) << 4);
                const __half* src = g_ua + (size_t)(w0 + kk + r) * D2 + i0 + c8 * 8;
                cp16(dst, src);
            } else {                      // B tile: 64 rows x 128B
                int j = idx - 1024;
                int r = j >> 3, c8 = j & 7;
                uint32_t dst = st + A_TILE + r * 128 + ((c8 ^ (r & 7)) << 4);
                const __half* src = g_Bh + (size_t)(n0 + r) * KDIM + p0 + c8 * 8;
                cp16(dst, src);
            }
        }
        CP_COMMIT();
    };

    issue_stage(0, 0);
    issue_stage(1, 1);
    issue_stage(2, 2);

    for (int ck = 0; ck < NK; ck++) {
        CP_WAIT2();
        __syncthreads();
        if (ck + 3 < NK) issue_stage(ck + 3, (ck + 3) % NSTAGE);
        else CP_COMMIT();

        uint32_t st = sb + (ck % NSTAGE) * STAGE_B;
        uint32_t aA = st, bH = st + A_TILE;
        #pragma unroll
        for (int ks = 0; ks < 4; ks++) {
            uint32_t ah[2][4];
            #pragma unroll
            for (int mf = 0; mf < 2; mf++) {
                int row = wm * 32 + mf * 16 + (lane & 7) + ((lane >> 3) & 1) * 8;
                int c = 2 * ks + (lane >> 4);
                uint32_t off = (uint32_t)(row * 128) + (uint32_t)((c ^ (row & 7)) << 4);
                ldmx4(ah[mf], aA + off);
            }
            #pragma unroll
            for (int bq = 0; bq < 2; bq++) {
                int row = wn * 32 + bq * 16 + (lane & 7) + ((lane >> 3) & 1) * 8;
                int c = 2 * ks + (lane >> 4);
                uint32_t off = (uint32_t)(row * 128) + (uint32_t)((c ^ (row & 7)) << 4);
                uint32_t bh[4];
                ldmx4(bh, bH + off);
                #pragma unroll
                for (int mf = 0; mf < 2; mf++) {
                    mma_f16(acc[mf][2 * bq],     ah[mf], bh[0], bh[2]);
                    mma_f16(acc[mf][2 * bq + 1], ah[mf], bh[1], bh[3]);
                }
            }
        }
    }

    // epilogue: column max over tile's 128 rows
    __syncthreads();
    float* red = (float*)smem;   // [4 wm][64 cols]
    #pragma unroll
    for (int f = 0; f < 4; f++) {
        float t0 = -1e30f, t1 = -1e30f;
        #pragma unroll
        for (int mf = 0; mf < 2; mf++) {
            t0 = fmaxf(t0, fmaxf(acc[mf][f][0], acc[mf][f][2]));
            t1 = fmaxf(t1, fmaxf(acc[mf][f][1], acc[mf][f][3]));
        }
        #pragma unroll
        for (int off = 4; off < 32; off <<= 1) {
            t0 = fmaxf(t0, __shfl_xor_sync(0xffffffffu, t0, off));
            t1 = fmaxf(t1, __shfl_xor_sync(0xffffffffu, t1, off));
        }
        if (lane < 4) {
            red[wm * 64 + wn * 32 + f * 8 + 2 * lane]     = t0;
            red[wm * 64 + wn * 32 + f * 8 + 2 * lane + 1] = t1;
        }
    }
    __syncthreads();
    if (tid < 64) {
        float m = red[tid];
        #pragma unroll
        for (int q = 1; q < 4; q++) m = fmaxf(m, red[q * 64 + tid]);
        unsigned u = __float_as_uint(m);
        unsigned key = (u & 0x80000000u) ? ~u : (u | 0x80000000u);
        atomicMax(&g_rkeys[n0 + tid], key);
    }
}

// ---------------- head: warp-per-output, float4 loads (MLP=4) ----------------
__global__ __launch_bounds__(256) void k_h(const float* __restrict__ sb,
                                           const float* __restrict__ w1,
                                           const float* __restrict__ b1) {
    __shared__ float rs[D2];
    int tid = threadIdx.x;         // 256 = 8 warps
    int lane = tid & 31, wp = tid >> 5;
    for (int j = tid; j < D2; j += 256) {
        unsigned key = g_rkeys[j];
        unsigned u = (key & 0x80000000u) ? (key & 0x7FFFFFFFu) : ~key;
        rs[j] = __uint_as_float(u) + sb[j];
    }
    __syncthreads();
    int o = blockIdx.x * 8 + wp;   // 128 blocks x 8 warps -> 1024 outputs
    const float4* W = (const float4*)(w1 + (size_t)o * D2);
    float4 v0 = W[lane];
    float4 v1 = W[lane + 32];
    float4 v2 = W[lane + 64];
    float4 v3 = W[lane + 96];
    const float4* R = (const float4*)rs;
    float4 r0 = R[lane];
    float4 r1 = R[lane + 32];
    float4 r2 = R[lane + 64];
    float4 r3 = R[lane + 96];
    float accv = v0.x * r0.x + v0.y * r0.y + v0.z * r0.z + v0.w * r0.w
               + v1.x * r1.x + v1.y * r1.y + v1.z * r1.z + v1.w * r1.w
               + v2.x * r2.x + v2.y * r2.y + v2.z * r2.z + v2.w * r2.w
               + v3.x * r3.x + v3.y * r3.y + v3.z * r3.z + v3.w * r3.w;
    #pragma unroll
    for (int off = 16; off; off >>= 1) accv += __shfl_down_sync(0xffffffffu, accv, off);
    if (lane == 0) g_h[o] = tanhf(accv + b1[o]);
}

__global__ void k_out(const float* __restrict__ w2,
                      const float* __restrict__ b2,
                      float* __restrict__ out) {
    int j = threadIdx.x >> 5, lane = threadIdx.x & 31;
    float accv = 0.f;
    for (int l = lane; l < D4; l += 32) accv += g_h[l] * w2[j * D4 + l];
    #pragma unroll
    for (int off = 16; off; off >>= 1) accv += __shfl_down_sync(0xffffffffu, accv, off);
    if (lane == 0) out[j] = accv + b2[j];
}

extern "C" void kernel_launch(void* const* d_in, const int* in_sizes, int n_in,
                              void* d_out, int out_size) {
    const int*   words       = (const int*)d_in[0];
    const int*   wic         = (const int*)d_in[1];
    const float* word_emb    = (const float*)d_in[2];
    const float* chr_emb     = (const float*)d_in[3];
    const float* conv_chr_w  = (const float*)d_in[4];
    const float* conv_chr_b  = (const float*)d_in[5];
    const float* conv_sent_w = (const float*)d_in[6];
    const float* conv_sent_b = (const float*)d_in[7];
    const float* w1          = (const float*)d_in[8];
    const float* b1          = (const float*)d_in[9];
    const float* w2          = (const float*)d_in[10];
    const float* b2          = (const float*)d_in[11];
    float* out = (float*)d_out;

    cudaFuncSetAttribute(k_gemm_mma, cudaFuncAttributeMaxDynamicSharedMemorySize, SMEM_DYN_GEMM);

    k_prep2<<<576, 256>>>(conv_chr_w, conv_sent_w, chr_emb);
    k_build_u<<<W_WORDS, 128>>>(words, wic, word_emb, conv_chr_b);
    dim3 g3(D2 / GN, W_WORDS / GM);     // 8 x 32 = 256 CTAs
    k_gemm_mma<<<g3, 256, SMEM_DYN_GEMM>>>();
    k_h<<<128, 256>>>(conv_sent_b, w1, b1);
    k_out<<<1, 64>>>(w2, b2, out);
}